// round 1
// baseline (speedup 1.0000x reference)
#include <cuda_runtime.h>

#define Bn   4
#define CIN  64
#define Hc   128
#define Wc   128
#define COUT 64
#define Kk   3
#define DGn  8
#define KKn  9
#define HOn  128
#define WOn  128
#define CGn  8

// Scratch (device globals; no runtime allocation allowed)
__device__ float g_xt[Bn * Hc * Wc * CIN];    // x transposed to NHWC: [b][y][x][c]
__device__ float g_wt[KKn * CIN * COUT];      // weight re-laid out:   [kk][c][o]

// ---------------------------------------------------------------------------
// x: [B, C, H*W]  ->  g_xt: [B, H*W, C]   (smem tiled transpose)
// ---------------------------------------------------------------------------
__global__ void transpose_x_kernel(const float* __restrict__ x) {
    __shared__ float tile[32][33];
    const int b  = blockIdx.z;
    const int c0 = blockIdx.y * 32;
    const int p0 = blockIdx.x * 32;
    const int tx = threadIdx.x, ty = threadIdx.y;

    #pragma unroll
    for (int j = 0; j < 32; j += 8)
        tile[ty + j][tx] = x[(size_t)(b * CIN + c0 + ty + j) * (Hc * Wc) + p0 + tx];
    __syncthreads();
    #pragma unroll
    for (int j = 0; j < 32; j += 8)
        g_xt[(size_t)(b * (Hc * Wc) + p0 + ty + j) * CIN + c0 + tx] = tile[tx][ty + j];
}

// ---------------------------------------------------------------------------
// weight: [COUT, CIN, K, K] -> g_wt[kk][c][o]
// ---------------------------------------------------------------------------
__global__ void transpose_w_kernel(const float* __restrict__ w) {
    int idx = blockIdx.x * 256 + threadIdx.x;
    if (idx >= KKn * CIN * COUT) return;
    int kk  = idx / (CIN * COUT);
    int rem = idx - kk * (CIN * COUT);
    int c   = rem / COUT;
    int o   = rem - c * COUT;
    g_wt[idx] = w[(size_t)(o * CIN + c) * KKn + kk];
}

// ---------------------------------------------------------------------------
// Fused deformable-conv kernel.
// Block = one output row (b, y): 128 pixels, all 64 outputs.
// For each kernel tap kk: sample 64ch x 128pix column chunk into smem (bilinear,
// NHWC vectorized gathers), then accumulate one GEMM step:
//   acc[o][pix] += cols[c][pix] * wt[kk][c][o]   (8o x 4pix register tile/thread)
// ---------------------------------------------------------------------------
__global__ void __launch_bounds__(256, 2) dcn_kernel(
    const float* __restrict__ offset,
    const float* __restrict__ bias,
    float* __restrict__ out)
{
    __shared__ __align__(16) float cols[CIN][WOn];   // 32 KB

    const int bid = blockIdx.x;          // 0 .. B*HO-1
    const int b   = bid >> 7;
    const int y   = bid & 127;
    const int tid = threadIdx.x;
    const int og  = tid >> 5;            // 0..7  -> outputs og*8 .. og*8+7
    const int pg  = tid & 31;            // 0..31 -> pixels  pg*4 .. pg*4+3

    float acc[8][4];
    #pragma unroll
    for (int i = 0; i < 8; ++i)
        #pragma unroll
        for (int j = 0; j < 4; ++j)
            acc[i][j] = 0.0f;

    const float* xt_b  = g_xt + (size_t)b * (Hc * Wc * CIN);
    const float* off_b = offset + (size_t)b * (2 * DGn * KKn * HOn * WOn) + (size_t)y * WOn;

    for (int kk = 0; kk < KKn; ++kk) {
        const int kh = kk / 3;
        const int kw = kk - kh * 3;

        // ---- sampling phase: 1024 points (8 dg x 128 pix), 4 per thread ----
        #pragma unroll
        for (int it = 0; it < 4; ++it) {
            const int t  = tid + it * 256;
            const int dg = t >> 7;
            const int px = t & 127;

            const float* op = off_b + (size_t)((dg * KKn + kk) * 2) * (HOn * WOn) + px;
            const float oy = op[0];
            const float ox = op[HOn * WOn];

            const float py  = (float)(y - 1 + kh) + oy;
            const float pxx = (float)(px - 1 + kw) + ox;
            const float y0f = floorf(py);
            const float x0f = floorf(pxx);
            const float ly  = py - y0f;
            const float lx  = pxx - x0f;
            const int y0 = (int)y0f;
            const int x0 = (int)x0f;
            const float hy = 1.0f - ly, hx = 1.0f - lx;

            float w00 = hy * hx, w01 = hy * lx, w10 = ly * hx, w11 = ly * lx;
            const bool yv0 = (y0 >= 0) && (y0 < Hc);
            const bool yv1 = (y0 + 1 >= 0) && (y0 + 1 < Hc);
            const bool xv0 = (x0 >= 0) && (x0 < Wc);
            const bool xv1 = (x0 + 1 >= 0) && (x0 + 1 < Wc);
            if (!(yv0 && xv0)) w00 = 0.0f;
            if (!(yv0 && xv1)) w01 = 0.0f;
            if (!(yv1 && xv0)) w10 = 0.0f;
            if (!(yv1 && xv1)) w11 = 0.0f;

            const int iy0 = min(max(y0, 0), Hc - 1);
            const int iy1 = min(max(y0 + 1, 0), Hc - 1);
            const int ix0 = min(max(x0, 0), Wc - 1);
            const int ix1 = min(max(x0 + 1, 0), Wc - 1);

            const float4* p00 = (const float4*)(xt_b + (size_t)(iy0 * Wc + ix0) * CIN + dg * CGn);
            const float4* p01 = (const float4*)(xt_b + (size_t)(iy0 * Wc + ix1) * CIN + dg * CGn);
            const float4* p10 = (const float4*)(xt_b + (size_t)(iy1 * Wc + ix0) * CIN + dg * CGn);
            const float4* p11 = (const float4*)(xt_b + (size_t)(iy1 * Wc + ix1) * CIN + dg * CGn);

            float* dst = &cols[dg * CGn][px];
            #pragma unroll
            for (int g = 0; g < 2; ++g) {
                const float4 v00 = p00[g];
                const float4 v01 = p01[g];
                const float4 v10 = p10[g];
                const float4 v11 = p11[g];
                dst[(g * 4 + 0) * WOn] = w00 * v00.x + w01 * v01.x + w10 * v10.x + w11 * v11.x;
                dst[(g * 4 + 1) * WOn] = w00 * v00.y + w01 * v01.y + w10 * v10.y + w11 * v11.y;
                dst[(g * 4 + 2) * WOn] = w00 * v00.z + w01 * v01.z + w10 * v10.z + w11 * v11.z;
                dst[(g * 4 + 3) * WOn] = w00 * v00.w + w01 * v01.w + w10 * v10.w + w11 * v11.w;
            }
        }
        __syncthreads();

        // ---- GEMM phase: acc[8][4] += wt[kk][c][og*8..+7] * cols[c][pg*4..+3] ----
        const float* wk = g_wt + (size_t)kk * (CIN * COUT) + og * 8;
        #pragma unroll 8
        for (int c = 0; c < CIN; ++c) {
            const float4 cv = *(const float4*)&cols[c][pg * 4];
            const float4 wa = *(const float4*)&wk[c * COUT];
            const float4 wb = *(const float4*)&wk[c * COUT + 4];
            acc[0][0] += wa.x * cv.x; acc[0][1] += wa.x * cv.y; acc[0][2] += wa.x * cv.z; acc[0][3] += wa.x * cv.w;
            acc[1][0] += wa.y * cv.x; acc[1][1] += wa.y * cv.y; acc[1][2] += wa.y * cv.z; acc[1][3] += wa.y * cv.w;
            acc[2][0] += wa.z * cv.x; acc[2][1] += wa.z * cv.y; acc[2][2] += wa.z * cv.z; acc[2][3] += wa.z * cv.w;
            acc[3][0] += wa.w * cv.x; acc[3][1] += wa.w * cv.y; acc[3][2] += wa.w * cv.z; acc[3][3] += wa.w * cv.w;
            acc[4][0] += wb.x * cv.x; acc[4][1] += wb.x * cv.y; acc[4][2] += wb.x * cv.z; acc[4][3] += wb.x * cv.w;
            acc[5][0] += wb.y * cv.x; acc[5][1] += wb.y * cv.y; acc[5][2] += wb.y * cv.z; acc[5][3] += wb.y * cv.w;
            acc[6][0] += wb.z * cv.x; acc[6][1] += wb.z * cv.y; acc[6][2] += wb.z * cv.z; acc[6][3] += wb.z * cv.w;
            acc[7][0] += wb.w * cv.x; acc[7][1] += wb.w * cv.y; acc[7][2] += wb.w * cv.z; acc[7][3] += wb.w * cv.w;
        }
        __syncthreads();
    }

    // ---- epilogue: add bias, vectorized stores ----
    #pragma unroll
    for (int j = 0; j < 8; ++j) {
        const int o = og * 8 + j;
        const float bv = bias[o];
        float4 r;
        r.x = acc[j][0] + bv;
        r.y = acc[j][1] + bv;
        r.z = acc[j][2] + bv;
        r.w = acc[j][3] + bv;
        *(float4*)&out[((size_t)(b * COUT + o) * HOn + y) * WOn + pg * 4] = r;
    }
}

extern "C" void kernel_launch(void* const* d_in, const int* in_sizes, int n_in,
                              void* d_out, int out_size) {
    const float* x      = (const float*)d_in[0];
    const float* offset = (const float*)d_in[1];
    const float* weight = (const float*)d_in[2];
    const float* bias   = (const float*)d_in[3];
    float* out = (float*)d_out;

    transpose_x_kernel<<<dim3((Hc * Wc) / 32, CIN / 32, Bn), dim3(32, 8)>>>(x);
    transpose_w_kernel<<<(KKn * CIN * COUT + 255) / 256, 256>>>(weight);
    dcn_kernel<<<Bn * HOn, 256>>>(offset, bias, out);
}

// round 2
// speedup vs baseline: 1.2408x; 1.2408x over previous
#include <cuda_runtime.h>

#define Bn   4
#define CIN  64
#define Hc   128
#define Wc   128
#define COUT 64
#define Kk   3
#define DGn  8
#define KKn  9
#define HOn  128
#define WOn  128
#define CGn  8

// Scratch (device globals; no runtime allocation allowed)
// x re-laid out per deformable group: [b][dg][y][x][cg]  (pixel stride = 32B)
__device__ float g_xt[Bn * DGn * Hc * Wc * CGn];
__device__ float g_wt[KKn * CIN * COUT];      // weight re-laid out: [kk][c][o]

// ---------------------------------------------------------------------------
// x: [B, C=dg*8+cg, H*W]  ->  g_xt: [b][dg][p][cg]
// ---------------------------------------------------------------------------
__global__ void transpose_x_kernel(const float* __restrict__ x) {
    __shared__ float s[8][260];                 // stride 260: (c*260+p)%32 = (4c+p)%32, conflict-free
    const int b   = blockIdx.z;
    const int dg  = blockIdx.y;
    const int p0  = blockIdx.x * 256;
    const int tid = threadIdx.x;

    #pragma unroll
    for (int ch = 0; ch < 8; ++ch)
        s[ch][tid] = x[(size_t)(b * CIN + dg * CGn + ch) * (Hc * Wc) + p0 + tid];
    __syncthreads();

    float* dst = g_xt + ((size_t)(b * DGn + dg) * (Hc * Wc) + p0) * CGn;
    #pragma unroll
    for (int i = 0; i < 8; ++i) {
        const int idx = i * 256 + tid;          // fully coalesced 32B-granular writes
        dst[idx] = s[idx & 7][idx >> 3];
    }
}

// ---------------------------------------------------------------------------
// weight: [COUT, CIN, K, K] -> g_wt[kk][c][o]
// ---------------------------------------------------------------------------
__global__ void transpose_w_kernel(const float* __restrict__ w) {
    int idx = blockIdx.x * 256 + threadIdx.x;
    if (idx >= KKn * CIN * COUT) return;
    int kk  = idx / (CIN * COUT);
    int rem = idx - kk * (CIN * COUT);
    int c   = rem / COUT;
    int o   = rem - c * COUT;
    g_wt[idx] = w[(size_t)(o * CIN + c) * KKn + kk];
}

// ---------------------------------------------------------------------------
// Fused deformable-conv kernel. Block = one output row (b, y).
// Per tap kk: bilinear-sample a 64ch x 128pix column chunk into smem (dg-blocked
// gathers, cross-lane coalesced), then one GEMM step with 8o x 4pix reg tiles.
// ---------------------------------------------------------------------------
__global__ void __launch_bounds__(256, 2) dcn_kernel(
    const float* __restrict__ offset,
    const float* __restrict__ bias,
    float* __restrict__ out)
{
    __shared__ __align__(16) float cols[CIN][WOn];   // 32 KB

    const int bid = blockIdx.x;          // 0 .. B*HO-1
    const int b   = bid >> 7;
    const int y   = bid & 127;
    const int tid = threadIdx.x;
    const int og  = tid >> 5;            // 0..7  -> outputs og*8 .. og*8+7
    const int pg  = tid & 31;            // 0..31 -> pixels  pg*4 .. pg*4+3

    float acc[8][4];
    #pragma unroll
    for (int i = 0; i < 8; ++i)
        #pragma unroll
        for (int j = 0; j < 4; ++j)
            acc[i][j] = 0.0f;

    const float* off_b = offset + (size_t)b * (2 * DGn * KKn * HOn * WOn) + (size_t)y * WOn;
    const float* xt_b  = g_xt + (size_t)b * (DGn * Hc * Wc * CGn);

    for (int kk = 0; kk < KKn; ++kk) {
        const int kh = kk / 3;
        const int kw = kk - kh * 3;

        // ---- sampling: 1024 points (8 dg x 128 px), 4 per thread ----
        #pragma unroll
        for (int it = 0; it < 4; ++it) {
            const int t  = tid + it * 256;
            const int dg = t >> 7;
            const int px = t & 127;

            const float* op = off_b + (size_t)((dg * KKn + kk) * 2) * (HOn * WOn) + px;
            const float oy = op[0];
            const float ox = op[HOn * WOn];

            const float py  = (float)(y - 1 + kh) + oy;
            const float pxx = (float)(px - 1 + kw) + ox;
            const float y0f = floorf(py);
            const float x0f = floorf(pxx);
            const float ly  = py - y0f;
            const float lx  = pxx - x0f;
            const int y0 = (int)y0f;
            const int x0 = (int)x0f;
            const float hy = 1.0f - ly, hx = 1.0f - lx;

            float w00 = hy * hx, w01 = hy * lx, w10 = ly * hx, w11 = ly * lx;
            const bool yv0 = (y0 >= 0) && (y0 < Hc);
            const bool yv1 = (y0 + 1 >= 0) && (y0 + 1 < Hc);
            const bool xv0 = (x0 >= 0) && (x0 < Wc);
            const bool xv1 = (x0 + 1 >= 0) && (x0 + 1 < Wc);
            if (!(yv0 && xv0)) w00 = 0.0f;
            if (!(yv0 && xv1)) w01 = 0.0f;
            if (!(yv1 && xv0)) w10 = 0.0f;
            if (!(yv1 && xv1)) w11 = 0.0f;

            const int iy0 = min(max(y0, 0), Hc - 1);
            const int iy1 = min(max(y0 + 1, 0), Hc - 1);
            const int ix0 = min(max(x0, 0), Wc - 1);
            const int ix1 = min(max(x0 + 1, 0), Wc - 1);

            // dg-blocked layout: 8 channels contiguous (32B) per pixel
            const float* xg = xt_b + (size_t)dg * (Hc * Wc * CGn);
            const float4* p00 = (const float4*)(xg + (size_t)(iy0 * Wc + ix0) * CGn);
            const float4* p01 = (const float4*)(xg + (size_t)(iy0 * Wc + ix1) * CGn);
            const float4* p10 = (const float4*)(xg + (size_t)(iy1 * Wc + ix0) * CGn);
            const float4* p11 = (const float4*)(xg + (size_t)(iy1 * Wc + ix1) * CGn);

            float* dst = &cols[dg * CGn][px];
            #pragma unroll
            for (int g = 0; g < 2; ++g) {
                const float4 v00 = p00[g];
                const float4 v01 = p01[g];
                const float4 v10 = p10[g];
                const float4 v11 = p11[g];
                dst[(g * 4 + 0) * WOn] = w00 * v00.x + w01 * v01.x + w10 * v10.x + w11 * v11.x;
                dst[(g * 4 + 1) * WOn] = w00 * v00.y + w01 * v01.y + w10 * v10.y + w11 * v11.y;
                dst[(g * 4 + 2) * WOn] = w00 * v00.z + w01 * v01.z + w10 * v10.z + w11 * v11.z;
                dst[(g * 4 + 3) * WOn] = w00 * v00.w + w01 * v01.w + w10 * v10.w + w11 * v11.w;
            }
        }
        __syncthreads();

        // ---- GEMM step: acc[8][4] += wt[kk][c][og*8..+7] * cols[c][pg*4..+3] ----
        const float* wk = g_wt + (size_t)kk * (CIN * COUT) + og * 8;
        #pragma unroll 8
        for (int c = 0; c < CIN; ++c) {
            const float4 cv = *(const float4*)&cols[c][pg * 4];
            const float4 wa = *(const float4*)&wk[c * COUT];
            const float4 wb = *(const float4*)&wk[c * COUT + 4];
            acc[0][0] += wa.x * cv.x; acc[0][1] += wa.x * cv.y; acc[0][2] += wa.x * cv.z; acc[0][3] += wa.x * cv.w;
            acc[1][0] += wa.y * cv.x; acc[1][1] += wa.y * cv.y; acc[1][2] += wa.y * cv.z; acc[1][3] += wa.y * cv.w;
            acc[2][0] += wa.z * cv.x; acc[2][1] += wa.z * cv.y; acc[2][2] += wa.z * cv.z; acc[2][3] += wa.z * cv.w;
            acc[3][0] += wa.w * cv.x; acc[3][1] += wa.w * cv.y; acc[3][2] += wa.w * cv.z; acc[3][3] += wa.w * cv.w;
            acc[4][0] += wb.x * cv.x; acc[4][1] += wb.x * cv.y; acc[4][2] += wb.x * cv.z; acc[4][3] += wb.x * cv.w;
            acc[5][0] += wb.y * cv.x; acc[5][1] += wb.y * cv.y; acc[5][2] += wb.y * cv.z; acc[5][3] += wb.y * cv.w;
            acc[6][0] += wb.z * cv.x; acc[6][1] += wb.z * cv.y; acc[6][2] += wb.z * cv.z; acc[6][3] += wb.z * cv.w;
            acc[7][0] += wb.w * cv.x; acc[7][1] += wb.w * cv.y; acc[7][2] += wb.w * cv.z; acc[7][3] += wb.w * cv.w;
        }
        __syncthreads();
    }

    // ---- epilogue: bias + vectorized stores ----
    #pragma unroll
    for (int j = 0; j < 8; ++j) {
        const int o = og * 8 + j;
        const float bv = bias[o];
        float4 r;
        r.x = acc[j][0] + bv;
        r.y = acc[j][1] + bv;
        r.z = acc[j][2] + bv;
        r.w = acc[j][3] + bv;
        *(float4*)&out[((size_t)(b * COUT + o) * HOn + y) * WOn + pg * 4] = r;
    }
}

extern "C" void kernel_launch(void* const* d_in, const int* in_sizes, int n_in,
                              void* d_out, int out_size) {
    const float* x      = (const float*)d_in[0];
    const float* offset = (const float*)d_in[1];
    const float* weight = (const float*)d_in[2];
    const float* bias   = (const float*)d_in[3];
    float* out = (float*)d_out;

    transpose_x_kernel<<<dim3((Hc * Wc) / 256, DGn, Bn), 256>>>(x);
    transpose_w_kernel<<<(KKn * CIN * COUT + 255) / 256, 256>>>(weight);
    dcn_kernel<<<Bn * HOn, 256>>>(offset, bias, out);
}